// round 1
// baseline (speedup 1.0000x reference)
#include <cuda_runtime.h>
#include <cuda_bf16.h>

// GeomAttention: B=2, L=S=2048, H=8, E=D=32, fp32.
// scores = (0.5*dot - 0.5*relu(qn2*kn2 - dot^2)) / sqrt(E); softmax over S; out = attn @ V.
// One query row per thread; K/V tiles staged in SMEM (all lanes broadcast-read the
// same key -> conflict-free). Packed fma.rn.f32x2 halves fma-pipe instruction count.

static constexpr int B_ = 2, L_ = 2048, H_ = 8, E_ = 32;
static constexpr int TS = 64;       // keys per SMEM tile
static constexpr int ROWS = 64;     // query rows per block
static constexpr int THREADS = 64;

typedef unsigned long long u64;

__device__ __forceinline__ u64 pk2(float a, float b) {
    u64 r; asm("mov.b64 %0, {%1,%2};" : "=l"(r) : "f"(a), "f"(b)); return r;
}
__device__ __forceinline__ float2 upk2(u64 v) {
    float2 r; asm("mov.b64 {%0,%1}, %2;" : "=f"(r.x), "=f"(r.y) : "l"(v)); return r;
}
__device__ __forceinline__ u64 ffma2(u64 a, u64 b, u64 c) {
    u64 d; asm("fma.rn.f32x2 %0, %1, %2, %3;" : "=l"(d) : "l"(a), "l"(b), "l"(c)); return d;
}
__device__ __forceinline__ u64 fmul2_(u64 a, u64 b) {
    u64 d; asm("mul.rn.f32x2 %0, %1, %2;" : "=l"(d) : "l"(a), "l"(b)); return d;
}

__global__ __launch_bounds__(THREADS) void geom_attn_kernel(
    const float* __restrict__ Q, const float* __restrict__ K,
    const float* __restrict__ V, float* __restrict__ O)
{
    __shared__ float4 sK[TS * 8];   // [TS][32 floats] as float4
    __shared__ float4 sV[TS * 8];
    __shared__ float  sKn2[TS];

    const int tid = threadIdx.x;
    const int l   = blockIdx.x * ROWS + tid;
    const int h   = blockIdx.y;
    const int b   = blockIdx.z;

    // Load this thread's query row (32 floats) into packed pairs; compute |q|^2.
    const float* qptr = Q + (((size_t)b * L_ + l) * H_ + h) * E_;
    u64 q2[16];
    float qn2 = 0.f;
    #pragma unroll
    for (int j = 0; j < 8; j++) {
        float4 t = ((const float4*)qptr)[j];
        q2[2*j]   = pk2(t.x, t.y);
        q2[2*j+1] = pk2(t.z, t.w);
        qn2 += t.x*t.x + t.y*t.y + t.z*t.z + t.w*t.w;
    }

    float m = -INFINITY, lsum = 0.f;
    u64 acc2[16];
    #pragma unroll
    for (int j = 0; j < 16; j++) acc2[j] = 0ull;

    const float scale = 0.5f * rsqrtf((float)E_);   // (alpha=0.5) / sqrt(E)

    const float* kbase = K + (((size_t)b * L_) * H_ + h) * E_;
    const float* vbase = V + (((size_t)b * L_) * H_ + h) * E_;

    for (int s0 = 0; s0 < L_; s0 += TS) {
        // Cooperative tile load: TS rows x 8 float4, coalesced within each row.
        #pragma unroll
        for (int i = tid; i < TS * 8; i += THREADS) {
            int r = i >> 3, j = i & 7;
            size_t off = (size_t)(s0 + r) * (H_ * E_);
            sK[i] = ((const float4*)(kbase + off))[j];
            sV[i] = ((const float4*)(vbase + off))[j];
        }
        __syncthreads();

        // Per-key squared norms (one key per thread; THREADS == TS).
        {
            float kn = 0.f;
            #pragma unroll
            for (int j = 0; j < 8; j++) {
                float4 kk = sK[tid * 8 + j];
                kn += kk.x*kk.x + kk.y*kk.y + kk.z*kk.z + kk.w*kk.w;
            }
            sKn2[tid] = kn;
        }
        __syncthreads();

        for (int s = 0; s < TS; s++) {
            // dot(q, k_s): two independent packed-pair chains for ILP.
            u64 d0 = 0ull, d1 = 0ull;
            #pragma unroll
            for (int j = 0; j < 8; j++) {
                float4 kk = sK[s * 8 + j];          // broadcast across warp
                d0 = ffma2(q2[2*j],   pk2(kk.x, kk.y), d0);
                d1 = ffma2(q2[2*j+1], pk2(kk.z, kk.w), d1);
            }
            float2 pa = upk2(d0), pb = upk2(d1);
            float dot = (pa.x + pa.y) + (pb.x + pb.y);

            float wedge = fmaxf(fmaf(qn2, sKn2[s], -dot * dot), 0.f);
            float sc = scale * (dot - wedge);

            // Online softmax with lazy rescale (max updates are rare).
            if (sc > m) {
                float c = __expf(m - sc);           // exp(-inf)=0 on first key
                lsum *= c;
                u64 cc = pk2(c, c);
                #pragma unroll
                for (int j = 0; j < 16; j++) acc2[j] = fmul2_(acc2[j], cc);
                m = sc;
            }
            float p = __expf(sc - m);
            lsum += p;

            u64 pp = pk2(p, p);
            #pragma unroll
            for (int j = 0; j < 8; j++) {
                float4 vv = sV[s * 8 + j];          // broadcast across warp
                acc2[2*j]   = ffma2(pp, pk2(vv.x, vv.y), acc2[2*j]);
                acc2[2*j+1] = ffma2(pp, pk2(vv.z, vv.w), acc2[2*j+1]);
            }
        }
        __syncthreads();
    }

    const float inv = 1.0f / lsum;
    float* optr = O + (((size_t)b * L_ + l) * H_ + h) * E_;
    #pragma unroll
    for (int j = 0; j < 8; j++) {
        float2 pa = upk2(acc2[2*j]), pb = upk2(acc2[2*j+1]);
        ((float4*)optr)[j] = make_float4(pa.x * inv, pa.y * inv, pb.x * inv, pb.y * inv);
    }
}

extern "C" void kernel_launch(void* const* d_in, const int* in_sizes, int n_in,
                              void* d_out, int out_size) {
    const float* Q = (const float*)d_in[0];
    const float* K = (const float*)d_in[1];
    const float* V = (const float*)d_in[2];
    float* O = (float*)d_out;
    (void)in_sizes; (void)n_in; (void)out_size;
    dim3 grid(L_ / ROWS, H_, B_);
    geom_attn_kernel<<<grid, THREADS>>>(Q, K, V, O);
}

// round 2
// speedup vs baseline: 1.2443x; 1.2443x over previous
#include <cuda_runtime.h>
#include <cuda_bf16.h>
#include <math_constants.h>

// GeomAttention: B=2, L=S=2048, H=8, E=D=32, fp32.
// scores = (0.5*dot - 0.5*relu(qn2*kn2 - dot^2)) / sqrt(E); softmax over S; out = attn @ V.
//
// R2: 2 query rows per thread (K/V smem reads amortized 2x, 2x ILP),
//     split-S = 4 with flash-decoding merge kernel (keeps 2048 warps in flight),
//     packed fma.rn.f32x2 throughout, single lazy-rescale branch per key.

static constexpr int B_ = 2, L_ = 2048, H_ = 8, E_ = 32;
static constexpr int SPLITS = 4;
static constexpr int SKEYS  = L_ / SPLITS;   // 512 keys per split
static constexpr int TS = 64;                // keys per SMEM tile
static constexpr int THREADS = 64;
static constexpr int ROWSPB = 2 * THREADS;   // 128 query rows per block (2 per thread)
static constexpr int NR = B_ * L_ * H_;      // 32768 total rows

__device__ float  g_m[SPLITS * NR];
__device__ float  g_l[SPLITS * NR];
__device__ float4 g_acc[SPLITS * NR * 8];

typedef unsigned long long u64;

__device__ __forceinline__ u64 pk2(float a, float b) {
    u64 r; asm("mov.b64 %0, {%1,%2};" : "=l"(r) : "f"(a), "f"(b)); return r;
}
__device__ __forceinline__ float2 upk2(u64 v) {
    float2 r; asm("mov.b64 {%0,%1}, %2;" : "=f"(r.x), "=f"(r.y) : "l"(v)); return r;
}
__device__ __forceinline__ u64 ffma2(u64 a, u64 b, u64 c) {
    u64 d; asm("fma.rn.f32x2 %0, %1, %2, %3;" : "=l"(d) : "l"(a), "l"(b), "l"(c)); return d;
}
__device__ __forceinline__ u64 fmul2_(u64 a, u64 b) {
    u64 d; asm("mul.rn.f32x2 %0, %1, %2;" : "=l"(d) : "l"(a), "l"(b)); return d;
}

__global__ __launch_bounds__(THREADS) void geom_attn_part(
    const float* __restrict__ Q, const float* __restrict__ K,
    const float* __restrict__ V)
{
    __shared__ float4 sK[TS * 8];
    __shared__ float4 sV[TS * 8];
    __shared__ float  sKn2[TS];

    const int tid   = threadIdx.x;
    const int h     = blockIdx.y;
    const int bz    = blockIdx.z;
    const int b     = bz >> 2;           // SPLITS == 4
    const int split = bz & 3;
    const int l0    = blockIdx.x * ROWSPB + tid;
    const int l1    = l0 + THREADS;

    // Load the two query rows into packed pairs; compute |q|^2 each.
    const float* qp0 = Q + (((size_t)b * L_ + l0) * H_ + h) * E_;
    const float* qp1 = Q + (((size_t)b * L_ + l1) * H_ + h) * E_;
    u64 qa[16], qb[16];
    float qn2a = 0.f, qn2b = 0.f;
    #pragma unroll
    for (int j = 0; j < 8; j++) {
        float4 t = ((const float4*)qp0)[j];
        qa[2*j] = pk2(t.x, t.y); qa[2*j+1] = pk2(t.z, t.w);
        qn2a += t.x*t.x + t.y*t.y + t.z*t.z + t.w*t.w;
        float4 u = ((const float4*)qp1)[j];
        qb[2*j] = pk2(u.x, u.y); qb[2*j+1] = pk2(u.z, u.w);
        qn2b += u.x*u.x + u.y*u.y + u.z*u.z + u.w*u.w;
    }

    float m0 = -CUDART_INF_F, m1 = -CUDART_INF_F, ls0 = 0.f, ls1 = 0.f;
    u64 acca[16], accb[16];
    #pragma unroll
    for (int j = 0; j < 16; j++) { acca[j] = 0ull; accb[j] = 0ull; }

    const float scale = 0.5f * rsqrtf((float)E_);

    const int key0 = split * SKEYS;
    const float* kbase = K + (((size_t)b * L_) * H_ + h) * E_;
    const float* vbase = V + (((size_t)b * L_) * H_ + h) * E_;

    for (int s0 = 0; s0 < SKEYS; s0 += TS) {
        #pragma unroll
        for (int i = tid; i < TS * 8; i += THREADS) {
            int r = i >> 3, j = i & 7;
            size_t off = (size_t)(key0 + s0 + r) * (H_ * E_);
            sK[i] = ((const float4*)(kbase + off))[j];
            sV[i] = ((const float4*)(vbase + off))[j];
        }
        __syncthreads();
        {
            float kn = 0.f;
            #pragma unroll
            for (int j = 0; j < 8; j++) {
                float4 kk = sK[tid * 8 + j];
                kn += kk.x*kk.x + kk.y*kk.y + kk.z*kk.z + kk.w*kk.w;
            }
            sKn2[tid] = kn;
        }
        __syncthreads();

        for (int s = 0; s < TS; s++) {
            // dots for both query rows: 4 independent packed chains.
            u64 a0 = 0ull, a1 = 0ull, b0 = 0ull, b1 = 0ull;
            #pragma unroll
            for (int j = 0; j < 8; j++) {
                float4 kk = sK[s * 8 + j];
                u64 klo = pk2(kk.x, kk.y), khi = pk2(kk.z, kk.w);
                a0 = ffma2(qa[2*j],   klo, a0);
                a1 = ffma2(qa[2*j+1], khi, a1);
                b0 = ffma2(qb[2*j],   klo, b0);
                b1 = ffma2(qb[2*j+1], khi, b1);
            }
            float2 ra0 = upk2(a0), ra1 = upk2(a1), rb0 = upk2(b0), rb1 = upk2(b1);
            float dota = (ra0.x + ra0.y) + (ra1.x + ra1.y);
            float dotb = (rb0.x + rb0.y) + (rb1.x + rb1.y);

            float kn2 = sKn2[s];
            float wa = fmaxf(fmaf(qn2a, kn2, -dota * dota), 0.f);
            float wb = fmaxf(fmaf(qn2b, kn2, -dotb * dotb), 0.f);
            float sca = scale * (dota - wa);
            float scb = scale * (dotb - wb);

            // Combined lazy rescale for both rows (exp(0)==1 exactly).
            if (sca > m0 || scb > m1) {
                float mna = fmaxf(m0, sca), mnb = fmaxf(m1, scb);
                float ca = __expf(m0 - mna), cb = __expf(m1 - mnb);
                ls0 *= ca; ls1 *= cb;
                u64 cca = pk2(ca, ca), ccb = pk2(cb, cb);
                #pragma unroll
                for (int j = 0; j < 16; j++) {
                    acca[j] = fmul2_(acca[j], cca);
                    accb[j] = fmul2_(accb[j], ccb);
                }
                m0 = mna; m1 = mnb;
            }
            float pa = __expf(sca - m0);
            float pb = __expf(scb - m1);
            ls0 += pa; ls1 += pb;

            u64 ppa = pk2(pa, pa), ppb = pk2(pb, pb);
            #pragma unroll
            for (int j = 0; j < 8; j++) {
                float4 vv = sV[s * 8 + j];
                u64 vlo = pk2(vv.x, vv.y), vhi = pk2(vv.z, vv.w);
                acca[2*j]   = ffma2(ppa, vlo, acca[2*j]);
                acca[2*j+1] = ffma2(ppa, vhi, acca[2*j+1]);
                accb[2*j]   = ffma2(ppb, vlo, accb[2*j]);
                accb[2*j+1] = ffma2(ppb, vhi, accb[2*j+1]);
            }
        }
        __syncthreads();
    }

    // Write partials (unnormalized, with per-split running max).
    const int r0 = ((b * L_ + l0) * H_ + h);
    const int r1 = ((b * L_ + l1) * H_ + h);
    g_m[split * NR + r0] = m0; g_l[split * NR + r0] = ls0;
    g_m[split * NR + r1] = m1; g_l[split * NR + r1] = ls1;
    float4* pa4 = &g_acc[(size_t)(split * NR + r0) * 8];
    float4* pb4 = &g_acc[(size_t)(split * NR + r1) * 8];
    #pragma unroll
    for (int j = 0; j < 8; j++) {
        float2 x = upk2(acca[2*j]), y = upk2(acca[2*j+1]);
        pa4[j] = make_float4(x.x, x.y, y.x, y.y);
        float2 u = upk2(accb[2*j]), v = upk2(accb[2*j+1]);
        pb4[j] = make_float4(u.x, u.y, v.x, v.y);
    }
}

// Merge: 8 threads per row (one float4 chunk each) for coalesced access.
__global__ __launch_bounds__(256) void geom_attn_merge(float* __restrict__ O)
{
    const int t = blockIdx.x * blockDim.x + threadIdx.x;   // 0 .. NR*8-1
    const int r = t >> 3;
    const int j = t & 7;

    float m = -CUDART_INF_F;
    #pragma unroll
    for (int s = 0; s < SPLITS; s++) m = fmaxf(m, g_m[s * NR + r]);

    float w[SPLITS];
    float denom = 0.f;
    #pragma unroll
    for (int s = 0; s < SPLITS; s++) {
        w[s] = __expf(g_m[s * NR + r] - m);
        denom = fmaf(w[s], g_l[s * NR + r], denom);
    }
    const float inv = 1.0f / denom;

    float4 o = make_float4(0.f, 0.f, 0.f, 0.f);
    #pragma unroll
    for (int s = 0; s < SPLITS; s++) {
        float4 a = g_acc[(size_t)(s * NR + r) * 8 + j];
        o.x = fmaf(w[s], a.x, o.x);
        o.y = fmaf(w[s], a.y, o.y);
        o.z = fmaf(w[s], a.z, o.z);
        o.w = fmaf(w[s], a.w, o.w);
    }
    o.x *= inv; o.y *= inv; o.z *= inv; o.w *= inv;
    ((float4*)O)[(size_t)r * 8 + j] = o;
}

extern "C" void kernel_launch(void* const* d_in, const int* in_sizes, int n_in,
                              void* d_out, int out_size) {
    const float* Q = (const float*)d_in[0];
    const float* K = (const float*)d_in[1];
    const float* V = (const float*)d_in[2];
    float* O = (float*)d_out;
    (void)in_sizes; (void)n_in; (void)out_size;

    dim3 grid(L_ / ROWSPB, H_, B_ * SPLITS);   // 16 x 8 x 8 = 1024 blocks
    geom_attn_part<<<grid, THREADS>>>(Q, K, V);
    geom_attn_merge<<<(NR * 8) / 256, 256>>>(O);
}

// round 3
// speedup vs baseline: 1.5636x; 1.2566x over previous
#include <cuda_runtime.h>
#include <cuda_bf16.h>
#include <math_constants.h>

// GeomAttention: B=2, L=S=2048, H=8, E=D=32, fp32.
// scores = (0.5*dot - 0.5*relu(qn2*kn2 - dot^2))/sqrt(E); softmax; out = attn @ V.
//
// R3: single fused kernel (split-S partials + last-block merge), SPLITS=2 for a
// single occupancy wave, 2 query rows/thread, chunk-8 scoring with one lazy
// rescale branch per chunk, direct u64 smem loads feeding fma.rn.f32x2.

static constexpr int B_ = 2, L_ = 2048, H_ = 8, E_ = 32;
static constexpr int SPLITS = 2;
static constexpr int SKEYS  = L_ / SPLITS;   // 1024
static constexpr int TS = 64;                // keys per SMEM tile
static constexpr int CH = 8;                 // keys per score chunk
static constexpr int THREADS = 64;
static constexpr int ROWSPB = 2 * THREADS;   // 128 rows per block
static constexpr int NR = B_ * L_ * H_;      // 32768 rows
static constexpr int NGROUPS = (L_ / ROWSPB) * H_ * B_;  // 256

__device__ float  g_m[SPLITS * NR];
__device__ float  g_l[SPLITS * NR];
__device__ float4 g_acc[SPLITS * NR * 8];
__device__ int    g_cnt[NGROUPS];            // zero-init; self-resetting

typedef unsigned long long u64;

__device__ __forceinline__ u64 pk2(float a, float b) {
    u64 r; asm("mov.b64 %0, {%1,%2};" : "=l"(r) : "f"(a), "f"(b)); return r;
}
__device__ __forceinline__ float2 upk2(u64 v) {
    float2 r; asm("mov.b64 {%0,%1}, %2;" : "=f"(r.x), "=f"(r.y) : "l"(v)); return r;
}
__device__ __forceinline__ u64 ffma2(u64 a, u64 b, u64 c) {
    u64 d; asm("fma.rn.f32x2 %0, %1, %2, %3;" : "=l"(d) : "l"(a), "l"(b), "l"(c)); return d;
}
__device__ __forceinline__ u64 fmul2_(u64 a, u64 b) {
    u64 d; asm("mul.rn.f32x2 %0, %1, %2;" : "=l"(d) : "l"(a), "l"(b)); return d;
}

__global__ __launch_bounds__(THREADS, 4) void geom_attn_fused(
    const float* __restrict__ Q, const float* __restrict__ K,
    const float* __restrict__ V, float* __restrict__ O)
{
    __shared__ float4 sK[TS * 8];
    __shared__ float4 sV[TS * 8];
    __shared__ float  sKn2[TS];
    __shared__ int    sLast;

    const int tid   = threadIdx.x;
    const int h     = blockIdx.y;
    const int bz    = blockIdx.z;
    const int b     = bz >> 1;                 // SPLITS == 2
    const int split = bz & 1;
    const int lbase = blockIdx.x * ROWSPB;
    const int l0    = lbase + tid;
    const int l1    = l0 + THREADS;

    // ---- load 2 query rows into packed pairs; |q|^2 each ----
    const float* qp0 = Q + (((size_t)b * L_ + l0) * H_ + h) * E_;
    const float* qp1 = Q + (((size_t)b * L_ + l1) * H_ + h) * E_;
    u64 qa[16], qb[16];
    float qn2a = 0.f, qn2b = 0.f;
    #pragma unroll
    for (int j = 0; j < 8; j++) {
        float4 t = ((const float4*)qp0)[j];
        qa[2*j] = pk2(t.x, t.y); qa[2*j+1] = pk2(t.z, t.w);
        qn2a += t.x*t.x + t.y*t.y + t.z*t.z + t.w*t.w;
        float4 u = ((const float4*)qp1)[j];
        qb[2*j] = pk2(u.x, u.y); qb[2*j+1] = pk2(u.z, u.w);
        qn2b += u.x*u.x + u.y*u.y + u.z*u.z + u.w*u.w;
    }

    float m0 = -CUDART_INF_F, m1 = -CUDART_INF_F, ls0 = 0.f, ls1 = 0.f;
    u64 acca[16], accb[16];
    #pragma unroll
    for (int j = 0; j < 16; j++) { acca[j] = 0ull; accb[j] = 0ull; }

    const float scale = 0.5f * rsqrtf((float)E_);
    const int key0 = split * SKEYS;
    const float* kbase = K + (((size_t)b * L_) * H_ + h) * E_;
    const float* vbase = V + (((size_t)b * L_) * H_ + h) * E_;

    for (int s0 = 0; s0 < SKEYS; s0 += TS) {
        #pragma unroll
        for (int i = tid; i < TS * 8; i += THREADS) {
            int r = i >> 3, j = i & 7;
            size_t off = (size_t)(key0 + s0 + r) * (H_ * E_);
            sK[i] = ((const float4*)(kbase + off))[j];
            sV[i] = ((const float4*)(vbase + off))[j];
        }
        __syncthreads();
        {   // per-key |k|^2 ; rotate j to avoid 32-way bank conflicts
            float kn = 0.f;
            #pragma unroll
            for (int jj = 0; jj < 8; jj++) {
                int j = (jj + tid) & 7;
                float4 kk = sK[tid * 8 + j];
                kn += kk.x*kk.x + kk.y*kk.y + kk.z*kk.z + kk.w*kk.w;
            }
            sKn2[tid] = kn;
        }
        __syncthreads();

        for (int c0 = 0; c0 < TS; c0 += CH) {
            float sa[CH], sb[CH];
            // ---- phase 1: scores for CH keys (both rows) ----
            #pragma unroll
            for (int u = 0; u < CH; u++) {
                const ulonglong2* kp = (const ulonglong2*)&sK[(c0 + u) * 8];
                u64 a0 = 0ull, a1 = 0ull, b0 = 0ull, b1 = 0ull;
                #pragma unroll
                for (int j = 0; j < 8; j++) {
                    ulonglong2 kk = kp[j];          // broadcast across warp
                    a0 = ffma2(qa[2*j],   kk.x, a0);
                    a1 = ffma2(qa[2*j+1], kk.y, a1);
                    b0 = ffma2(qb[2*j],   kk.x, b0);
                    b1 = ffma2(qb[2*j+1], kk.y, b1);
                }
                float2 ra0 = upk2(a0), ra1 = upk2(a1);
                float2 rb0 = upk2(b0), rb1 = upk2(b1);
                float dota = (ra0.x + ra0.y) + (ra1.x + ra1.y);
                float dotb = (rb0.x + rb0.y) + (rb1.x + rb1.y);
                float kn2  = sKn2[c0 + u];
                float wa = fmaxf(fmaf(qn2a, kn2, -dota * dota), 0.f);
                float wb = fmaxf(fmaf(qn2b, kn2, -dotb * dotb), 0.f);
                sa[u] = scale * (dota - wa);
                sb[u] = scale * (dotb - wb);
            }
            // ---- chunk max + single lazy rescale ----
            float cma = sa[0], cmb = sb[0];
            #pragma unroll
            for (int u = 1; u < CH; u++) { cma = fmaxf(cma, sa[u]); cmb = fmaxf(cmb, sb[u]); }
            if (cma > m0 || cmb > m1) {
                float mna = fmaxf(m0, cma), mnb = fmaxf(m1, cmb);
                float ca = __expf(m0 - mna), cb = __expf(m1 - mnb);
                ls0 *= ca; ls1 *= cb;
                u64 cca = pk2(ca, ca), ccb = pk2(cb, cb);
                #pragma unroll
                for (int j = 0; j < 16; j++) {
                    acca[j] = fmul2_(acca[j], cca);
                    accb[j] = fmul2_(accb[j], ccb);
                }
                m0 = mna; m1 = mnb;
            }
            // ---- phase 2: exp + PV accumulate (branchless) ----
            #pragma unroll
            for (int u = 0; u < CH; u++) {
                float pa = __expf(sa[u] - m0);
                float pb = __expf(sb[u] - m1);
                ls0 += pa; ls1 += pb;
                u64 ppa = pk2(pa, pa), ppb = pk2(pb, pb);
                const ulonglong2* vp = (const ulonglong2*)&sV[(c0 + u) * 8];
                #pragma unroll
                for (int j = 0; j < 8; j++) {
                    ulonglong2 vv = vp[j];
                    acca[2*j]   = ffma2(ppa, vv.x, acca[2*j]);
                    acca[2*j+1] = ffma2(ppa, vv.y, acca[2*j+1]);
                    accb[2*j]   = ffma2(ppb, vv.x, accb[2*j]);
                    accb[2*j+1] = ffma2(ppb, vv.y, accb[2*j+1]);
                }
            }
        }
        __syncthreads();
    }

    // ---- write partials ----
    const int r0 = ((b * L_ + l0) * H_ + h);
    const int r1 = ((b * L_ + l1) * H_ + h);
    g_m[split * NR + r0] = m0; g_l[split * NR + r0] = ls0;
    g_m[split * NR + r1] = m1; g_l[split * NR + r1] = ls1;
    float4* pa4 = &g_acc[(size_t)(split * NR + r0) * 8];
    float4* pb4 = &g_acc[(size_t)(split * NR + r1) * 8];
    #pragma unroll
    for (int j = 0; j < 8; j++) {
        float2 x = upk2(acca[2*j]), y = upk2(acca[2*j+1]);
        pa4[j] = make_float4(x.x, x.y, y.x, y.y);
        float2 u = upk2(accb[2*j]), v = upk2(accb[2*j+1]);
        pb4[j] = make_float4(u.x, u.y, v.x, v.y);
    }

    // ---- last block of this group merges the splits ----
    const int g = blockIdx.x + (L_ / ROWSPB) * (h + H_ * b);
    __threadfence();
    if (tid == 0) {
        int prev = atomicAdd(&g_cnt[g], 1);
        sLast = (prev == SPLITS - 1);
    }
    __syncthreads();
    if (!sLast) return;
    __threadfence();

    // 64 threads merge 128 rows: 8 threads per row (one float4 chunk each).
    #pragma unroll 1
    for (int it = 0; it < ROWSPB / 8; it++) {
        int rl = it * 8 + (tid >> 3);
        int jj = tid & 7;
        int r  = ((b * L_ + lbase + rl) * H_ + h);
        float mA = g_m[r], mB = g_m[NR + r];
        float mm = fmaxf(mA, mB);
        float w0 = __expf(mA - mm), w1 = __expf(mB - mm);
        float denom = w0 * g_l[r] + w1 * g_l[NR + r];
        float inv = 1.0f / denom;
        float4 a0 = g_acc[(size_t)r * 8 + jj];
        float4 a1 = g_acc[(size_t)(NR + r) * 8 + jj];
        float4 o;
        o.x = (w0 * a0.x + w1 * a1.x) * inv;
        o.y = (w0 * a0.y + w1 * a1.y) * inv;
        o.z = (w0 * a0.z + w1 * a1.z) * inv;
        o.w = (w0 * a0.w + w1 * a1.w) * inv;
        ((float4*)O)[(size_t)r * 8 + jj] = o;
    }
    if (tid == 0) g_cnt[g] = 0;   // self-reset for next graph replay
}

extern "C" void kernel_launch(void* const* d_in, const int* in_sizes, int n_in,
                              void* d_out, int out_size) {
    const float* Q = (const float*)d_in[0];
    const float* K = (const float*)d_in[1];
    const float* V = (const float*)d_in[2];
    float* O = (float*)d_out;
    (void)in_sizes; (void)n_in; (void)out_size;
    dim3 grid(L_ / ROWSPB, H_, B_ * SPLITS);   // 16 x 8 x 4 = 512 blocks
    geom_attn_fused<<<grid, THREADS>>>(Q, K, V, O);
}